// round 1
// baseline (speedup 1.0000x reference)
#include <cuda_runtime.h>
#include <math.h>

#define T_    128
#define B_    1024
#define LAG_  6
#define H_    256
#define G_    1024            // 4*H
#define NR_   (T_*B_)         // 131072
#define BH_   (B_*H_)         // 262144

// ---------------- scratch (device globals; no allocation allowed) ----------
__device__ float g_bufA[NR_*H_];            // 134 MB ping
__device__ float g_bufB[NR_*H_];            // 134 MB pong
__device__ float g_A0[(size_t)NR_*G_];      // 536 MB precomputed input gates (layer0)
__device__ float g_hs[NR_*H_];              // 134 MB layer-1 h per timestep
__device__ float g_h0[2*BH_];
__device__ float g_c0[2*BH_];
__device__ float g_c1[2*BH_];
__device__ float g_zeros[BH_];
__device__ float g_Wih0r[G_*H_];            // gate-interleaved reorder
__device__ float g_Whh0r[G_*H_];
__device__ float g_W1r[G_*2*H_];            // [1024][512]: [Wih1 | Whh1] reordered
__device__ float g_b0r[G_];
__device__ float g_b1r[G_];

// ---------------- prep: gate-interleave weight reorder ---------------------
// dst row r = 4*j + g  <-  src row g*H + j   (gates of hidden j adjacent)
__global__ void k_prep(const float* __restrict__ Wih0, const float* __restrict__ Whh0,
                       const float* __restrict__ bih0, const float* __restrict__ bhh0,
                       const float* __restrict__ Wih1, const float* __restrict__ Whh1,
                       const float* __restrict__ bih1, const float* __restrict__ bhh1) {
    int idx = blockIdx.x * blockDim.x + threadIdx.x;
    int total = G_ * H_;
    for (int i = idx; i < total; i += gridDim.x * blockDim.x) {
        int r = i / H_, k = i - r * H_;
        int j = r >> 2, g = r & 3;
        int src = (g * H_ + j) * H_ + k;
        g_Wih0r[i] = Wih0[src];
        g_Whh0r[i] = Whh0[src];
        g_W1r[r * (2 * H_) + k]       = Wih1[src];
        g_W1r[r * (2 * H_) + H_ + k]  = Whh1[src];
    }
    if (idx < G_) {
        int j = idx >> 2, g = idx & 3;
        g_b0r[idx] = bih0[g * H_ + j] + bhh0[g * H_ + j];
        g_b1r[idx] = bih1[g * H_ + j] + bhh1[g * H_ + j];
    }
}

__global__ void k_zero() {
    int idx = blockIdx.x * blockDim.x + threadIdx.x;
    for (int i = idx; i < BH_; i += gridDim.x * blockDim.x) {
        g_zeros[i] = 0.f;
        g_h0[i] = 0.f;
        g_c0[i] = 0.f;
        g_c1[i] = 0.f;
    }
}

// ---------------- input MLP stage 1 (K=6) ----------------------------------
__global__ void k_in1(const float* __restrict__ x, const float* __restrict__ Wi1,
                      const float* __restrict__ bi1, float* __restrict__ u) {
    int row = blockIdx.x;
    __shared__ float xs[LAG_];
    if (threadIdx.x < LAG_) xs[threadIdx.x] = x[row * LAG_ + threadIdx.x];
    __syncthreads();
    int j = threadIdx.x;
    float acc = bi1[j];
#pragma unroll
    for (int k = 0; k < LAG_; k++) acc = fmaf(xs[k], Wi1[j * LAG_ + k], acc);
    u[(size_t)row * H_ + j] = fmaxf(acc, 0.f);
}

// ---------------- generic tiled fp32 GEMM: C = act(A @ W^T + bias) ---------
// A[M,K] row-major, W[N,K] row-major. BM=BN=64, BK=16, 256 thr, 4x4/thread.
template<bool RELU, bool BIAS, bool RELU_A>
__global__ void __launch_bounds__(256)
k_gemm(const float* __restrict__ A, const float* __restrict__ W,
       const float* __restrict__ bias, float* __restrict__ C,
       int M, int N, int K) {
    __shared__ float As[16][64];
    __shared__ float Ws[16][64];
    int tid = threadIdx.x;
    int bm = blockIdx.y * 64, bn = blockIdx.x * 64;
    int lr = tid >> 2, lc = (tid & 3) << 2;
    int ty = tid >> 4, tx = tid & 15;
    float acc[4][4] = {};
    const float* Arow = A + (size_t)(bm + lr) * K;
    const float* Wrow = W + (size_t)(bn + lr) * K;
    for (int k0 = 0; k0 < K; k0 += 16) {
        float4 a4 = *(const float4*)(Arow + k0 + lc);
        float4 w4 = *(const float4*)(Wrow + k0 + lc);
        if (RELU_A) {
            a4.x = fmaxf(a4.x, 0.f); a4.y = fmaxf(a4.y, 0.f);
            a4.z = fmaxf(a4.z, 0.f); a4.w = fmaxf(a4.w, 0.f);
        }
        As[lc + 0][lr] = a4.x; As[lc + 1][lr] = a4.y;
        As[lc + 2][lr] = a4.z; As[lc + 3][lr] = a4.w;
        Ws[lc + 0][lr] = w4.x; Ws[lc + 1][lr] = w4.y;
        Ws[lc + 2][lr] = w4.z; Ws[lc + 3][lr] = w4.w;
        __syncthreads();
#pragma unroll
        for (int kk = 0; kk < 16; kk++) {
            float4 ra = *(const float4*)&As[kk][ty << 2];
            float4 rb = *(const float4*)&Ws[kk][tx << 2];
            acc[0][0] = fmaf(ra.x, rb.x, acc[0][0]); acc[0][1] = fmaf(ra.x, rb.y, acc[0][1]);
            acc[0][2] = fmaf(ra.x, rb.z, acc[0][2]); acc[0][3] = fmaf(ra.x, rb.w, acc[0][3]);
            acc[1][0] = fmaf(ra.y, rb.x, acc[1][0]); acc[1][1] = fmaf(ra.y, rb.y, acc[1][1]);
            acc[1][2] = fmaf(ra.y, rb.z, acc[1][2]); acc[1][3] = fmaf(ra.y, rb.w, acc[1][3]);
            acc[2][0] = fmaf(ra.z, rb.x, acc[2][0]); acc[2][1] = fmaf(ra.z, rb.y, acc[2][1]);
            acc[2][2] = fmaf(ra.z, rb.z, acc[2][2]); acc[2][3] = fmaf(ra.z, rb.w, acc[2][3]);
            acc[3][0] = fmaf(ra.w, rb.x, acc[3][0]); acc[3][1] = fmaf(ra.w, rb.y, acc[3][1]);
            acc[3][2] = fmaf(ra.w, rb.z, acc[3][2]); acc[3][3] = fmaf(ra.w, rb.w, acc[3][3]);
        }
        __syncthreads();
    }
#pragma unroll
    for (int i = 0; i < 4; i++) {
        float* Crow = C + (size_t)(bm + (ty << 2) + i) * N + bn + (tx << 2);
        float4 v;
        float* vp = &v.x;
#pragma unroll
        for (int j = 0; j < 4; j++) {
            float t = acc[i][j];
            if (BIAS) t += bias[bn + (tx << 2) + j];
            if (RELU) t = fmaxf(t, 0.f);
            vp[j] = t;
        }
        *(float4*)Crow = v;
    }
}

// ---------------- fused LSTM step: GEMM + cell epilogue --------------------
// gates = [Aa | Ab] @ Wr^T + (addend row slice | brow); gate-interleaved cols.
// Each thread's 4-wide col fragment = one hidden unit's (i,f,g,o).
__global__ void __launch_bounds__(256)
k_step(const float* __restrict__ Aa, const float* __restrict__ Ab,
       const float* __restrict__ Wr, int K,
       const float* __restrict__ addend, const float* __restrict__ brow,
       const float* __restrict__ c_prev, float* __restrict__ c_new,
       float* __restrict__ h_out) {
    __shared__ float As[16][64];
    __shared__ float Ws[16][64];
    int tid = threadIdx.x;
    int bm = blockIdx.y * 64, bn = blockIdx.x * 64;
    int lr = tid >> 2, lc = (tid & 3) << 2;
    int ty = tid >> 4, tx = tid & 15;
    float acc[4][4] = {};
    const float* Wrow = Wr + (size_t)(bn + lr) * K;
    for (int k0 = 0; k0 < K; k0 += 16) {
        const float* Asrc = (k0 < H_) ? Aa : Ab;
        int ak = (k0 < H_) ? k0 : (k0 - H_);
        float4 a4 = *(const float4*)(Asrc + (size_t)(bm + lr) * H_ + ak + lc);
        float4 w4 = *(const float4*)(Wrow + k0 + lc);
        As[lc + 0][lr] = a4.x; As[lc + 1][lr] = a4.y;
        As[lc + 2][lr] = a4.z; As[lc + 3][lr] = a4.w;
        Ws[lc + 0][lr] = w4.x; Ws[lc + 1][lr] = w4.y;
        Ws[lc + 2][lr] = w4.z; Ws[lc + 3][lr] = w4.w;
        __syncthreads();
#pragma unroll
        for (int kk = 0; kk < 16; kk++) {
            float4 ra = *(const float4*)&As[kk][ty << 2];
            float4 rb = *(const float4*)&Ws[kk][tx << 2];
            acc[0][0] = fmaf(ra.x, rb.x, acc[0][0]); acc[0][1] = fmaf(ra.x, rb.y, acc[0][1]);
            acc[0][2] = fmaf(ra.x, rb.z, acc[0][2]); acc[0][3] = fmaf(ra.x, rb.w, acc[0][3]);
            acc[1][0] = fmaf(ra.y, rb.x, acc[1][0]); acc[1][1] = fmaf(ra.y, rb.y, acc[1][1]);
            acc[1][2] = fmaf(ra.y, rb.z, acc[1][2]); acc[1][3] = fmaf(ra.y, rb.w, acc[1][3]);
            acc[2][0] = fmaf(ra.z, rb.x, acc[2][0]); acc[2][1] = fmaf(ra.z, rb.y, acc[2][1]);
            acc[2][2] = fmaf(ra.z, rb.z, acc[2][2]); acc[2][3] = fmaf(ra.z, rb.w, acc[2][3]);
            acc[3][0] = fmaf(ra.w, rb.x, acc[3][0]); acc[3][1] = fmaf(ra.w, rb.y, acc[3][1]);
            acc[3][2] = fmaf(ra.w, rb.z, acc[3][2]); acc[3][3] = fmaf(ra.w, rb.w, acc[3][3]);
        }
        __syncthreads();
    }
    int jh = (bn >> 2) + tx;   // hidden-unit index for this thread's 4 columns
#pragma unroll
    for (int i = 0; i < 4; i++) {
        int row = bm + (ty << 2) + i;
        float gg[4];
        if (addend) {
            const float* ar = addend + (size_t)row * G_ + bn + (tx << 2);
#pragma unroll
            for (int q = 0; q < 4; q++) gg[q] = acc[i][q] + ar[q];
        } else {
#pragma unroll
            for (int q = 0; q < 4; q++) gg[q] = acc[i][q] + brow[bn + (tx << 2) + q];
        }
        float iG = 1.f / (1.f + expf(-gg[0]));
        float fG = 1.f / (1.f + expf(-gg[1]));
        float gN = tanhf(gg[2]);
        float oG = 1.f / (1.f + expf(-gg[3]));
        float c  = fmaf(fG, c_prev[row * H_ + jh], iG * gN);
        c_new[row * H_ + jh] = c;
        h_out[row * H_ + jh] = oG * tanhf(c);
    }
}

// ---------------- output head (N=6) ----------------------------------------
__global__ void k_out3(const float* __restrict__ Ain, const float* __restrict__ Wo3,
                       const float* __restrict__ bo3, float* __restrict__ y) {
    int row = blockIdx.x;
    int o = threadIdx.x >> 5, lane = threadIdx.x & 31;
    float acc = 0.f;
    const float* ar = Ain + (size_t)row * H_;
    const float* wr = Wo3 + o * H_;
#pragma unroll
    for (int k = lane; k < H_; k += 32) acc = fmaf(ar[k], wr[k], acc);
#pragma unroll
    for (int off = 16; off; off >>= 1) acc += __shfl_xor_sync(0xffffffffu, acc, off);
    if (lane == 0) y[row * LAG_ + o] = acc + bo3[o];
}

// ---------------- host ------------------------------------------------------
extern "C" void kernel_launch(void* const* d_in, const int* in_sizes, int n_in,
                              void* d_out, int out_size) {
    const float* x    = (const float*)d_in[0];
    const float* Wi1  = (const float*)d_in[1];  const float* bi1 = (const float*)d_in[2];
    const float* Wi2  = (const float*)d_in[3];  const float* bi2 = (const float*)d_in[4];
    const float* Wi3  = (const float*)d_in[5];  const float* bi3 = (const float*)d_in[6];
    const float* Wih0 = (const float*)d_in[7];  const float* Whh0 = (const float*)d_in[8];
    const float* bih0 = (const float*)d_in[9];  const float* bhh0 = (const float*)d_in[10];
    const float* Wih1 = (const float*)d_in[11]; const float* Whh1 = (const float*)d_in[12];
    const float* bih1 = (const float*)d_in[13]; const float* bhh1 = (const float*)d_in[14];
    const float* Wo1  = (const float*)d_in[15]; const float* bo1 = (const float*)d_in[16];
    const float* Wo2  = (const float*)d_in[17]; const float* bo2 = (const float*)d_in[18];
    const float* Wo3  = (const float*)d_in[19]; const float* bo3 = (const float*)d_in[20];
    float* y = (float*)d_out;

    float *bufA, *bufB, *A0, *hs, *h0b, *c0b, *c1b, *zeros;
    float *Wih0r, *Whh0r, *W1r, *b0r, *b1r;
    cudaGetSymbolAddress((void**)&bufA,  g_bufA);
    cudaGetSymbolAddress((void**)&bufB,  g_bufB);
    cudaGetSymbolAddress((void**)&A0,    g_A0);
    cudaGetSymbolAddress((void**)&hs,    g_hs);
    cudaGetSymbolAddress((void**)&h0b,   g_h0);
    cudaGetSymbolAddress((void**)&c0b,   g_c0);
    cudaGetSymbolAddress((void**)&c1b,   g_c1);
    cudaGetSymbolAddress((void**)&zeros, g_zeros);
    cudaGetSymbolAddress((void**)&Wih0r, g_Wih0r);
    cudaGetSymbolAddress((void**)&Whh0r, g_Whh0r);
    cudaGetSymbolAddress((void**)&W1r,   g_W1r);
    cudaGetSymbolAddress((void**)&b0r,   g_b0r);
    cudaGetSymbolAddress((void**)&b1r,   g_b1r);

    k_prep<<<512, 512>>>(Wih0, Whh0, bih0, bhh0, Wih1, Whh1, bih1, bhh1);
    k_zero<<<512, 512>>>();

    // input MLP
    k_in1<<<NR_, H_>>>(x, Wi1, bi1, bufA);
    dim3 blk(256);
    dim3 gBig(H_ / 64, NR_ / 64);                 // (4, 2048)
    k_gemm<true, true, false><<<gBig, blk>>>(bufA, Wi2, bi2, bufB, NR_, H_, H_);
    k_gemm<true, true, false><<<gBig, blk>>>(bufB, Wi3, bi3, bufA, NR_, H_, H_);

    // hoisted layer-0 input projection over all timesteps: A0 = u @ Wih0r^T + b0r
    dim3 gA0(G_ / 64, NR_ / 64);                  // (16, 2048)
    k_gemm<false, true, false><<<gA0, blk>>>(bufA, Wih0r, b0r, A0, NR_, G_, H_);

    // sequential recurrence
    dim3 gStep(G_ / 64, B_ / 64);                 // (16, 16)
    for (int t = 0; t < T_; t++) {
        int r = t & 1, w = 1 - r;
        const float* h1p = (t == 0) ? zeros : hs + (size_t)(t - 1) * BH_;
        // layer 0: gates = h0_prev @ Whh0r^T + A0[t]  -> h0_new, c0_new
        k_step<<<gStep, blk>>>(h0b + r * BH_, h0b + r * BH_, Whh0r, H_,
                               A0 + (size_t)t * B_ * G_, nullptr,
                               c0b + r * BH_, c0b + w * BH_, h0b + w * BH_);
        // layer 1: gates = [h0_new | h1_prev] @ W1r^T + b1r -> hs[t], c1_new
        k_step<<<gStep, blk>>>(h0b + w * BH_, h1p, W1r, 2 * H_,
                               nullptr, b1r,
                               c1b + r * BH_, c1b + w * BH_, hs + (size_t)t * BH_);
    }

    // output MLP (relu applied to hs at load)
    k_gemm<true, true, true ><<<gBig, blk>>>(hs,   Wo1, bo1, bufA, NR_, H_, H_);
    k_gemm<true, true, false><<<gBig, blk>>>(bufA, Wo2, bo2, bufB, NR_, H_, H_);
    k_out3<<<NR_, 192>>>(bufB, Wo3, bo3, y);
}

// round 3
// speedup vs baseline: 1.5139x; 1.5139x over previous
#include <cuda_runtime.h>
#include <cuda_bf16.h>
#include <math.h>
#include <stdint.h>

#define T_    128
#define B_    1024
#define LAG_  6
#define H_    256
#define G_    1024            // 4*H
#define NR_   (T_*B_)         // 131072
#define BH_   (B_*H_)         // 262144

typedef __nv_bfloat16 bf16;

// ============================ device scratch ================================
__device__ float g_A0[(size_t)NR_*G_];          // 536 MB input-gate precompute
__device__ float g_bufB[NR_*H_];                // f32 staging before out3
__device__ bf16 g_u_hi[NR_*H_],  g_u_lo[NR_*H_];
__device__ bf16 g_v_hi[NR_*H_],  g_v_lo[NR_*H_];
__device__ bf16 g_hsr_hi[NR_*H_], g_hsr_lo[NR_*H_];   // relu(h1) split, per t
__device__ bf16 g_h0_hi[2*BH_], g_h0_lo[2*BH_];
__device__ bf16 g_h1_hi[2*BH_], g_h1_lo[2*BH_];
__device__ float g_c0[2*BH_], g_c1[2*BH_];
// split weights (row-major [N][K])
__device__ bf16 g_Wi2_hi[H_*H_], g_Wi2_lo[H_*H_];
__device__ bf16 g_Wi3_hi[H_*H_], g_Wi3_lo[H_*H_];
__device__ bf16 g_Wo1_hi[H_*H_], g_Wo1_lo[H_*H_];
__device__ bf16 g_Wo2_hi[H_*H_], g_Wo2_lo[H_*H_];
__device__ bf16 g_Wih0_hi[G_*H_], g_Wih0_lo[G_*H_];   // gate-interleaved rows
__device__ bf16 g_Whh0_hi[G_*H_], g_Whh0_lo[G_*H_];
__device__ bf16 g_W1_hi[G_*2*H_], g_W1_lo[G_*2*H_];   // [1024][512] = [Wih1|Whh1]
__device__ float g_b0r[G_], g_b1r[G_];

// ======================= prep: split + gate reorder =========================
__device__ __forceinline__ void split_store(bf16* hi, bf16* lo, size_t i, float v) {
    bf16 h = __float2bfloat16(v);
    hi[i] = h;
    lo[i] = __float2bfloat16(v - __bfloat162float(h));
}

__global__ void k_prep(const float* __restrict__ Wi2, const float* __restrict__ Wi3,
                       const float* __restrict__ Wo1, const float* __restrict__ Wo2,
                       const float* __restrict__ Wih0, const float* __restrict__ Whh0,
                       const float* __restrict__ bih0, const float* __restrict__ bhh0,
                       const float* __restrict__ Wih1, const float* __restrict__ Whh1,
                       const float* __restrict__ bih1, const float* __restrict__ bhh1) {
    int idx = blockIdx.x * blockDim.x + threadIdx.x;
    int stride = gridDim.x * blockDim.x;
    for (int i = idx; i < H_ * H_; i += stride) {
        split_store(g_Wi2_hi, g_Wi2_lo, i, Wi2[i]);
        split_store(g_Wi3_hi, g_Wi3_lo, i, Wi3[i]);
        split_store(g_Wo1_hi, g_Wo1_lo, i, Wo1[i]);
        split_store(g_Wo2_hi, g_Wo2_lo, i, Wo2[i]);
    }
    for (int i = idx; i < G_ * H_; i += stride) {       // layer-0, gate-interleaved
        int r = i / H_, k = i - r * H_;
        int j = r >> 2, g = r & 3;
        int src = (g * H_ + j) * H_ + k;
        split_store(g_Wih0_hi, g_Wih0_lo, i, Wih0[src]);
        split_store(g_Whh0_hi, g_Whh0_lo, i, Whh0[src]);
    }
    for (int i = idx; i < G_ * 2 * H_; i += stride) {   // layer-1 concat
        int r = i / (2 * H_), k = i - r * (2 * H_);
        int j = r >> 2, g = r & 3;
        float v = (k < H_) ? Wih1[(g * H_ + j) * H_ + k]
                           : Whh1[(g * H_ + j) * H_ + (k - H_)];
        split_store(g_W1_hi, g_W1_lo, i, v);
    }
    if (idx < G_) {
        int j = idx >> 2, g = idx & 3;
        g_b0r[idx] = bih0[g * H_ + j] + bhh0[g * H_ + j];
        g_b1r[idx] = bih1[g * H_ + j] + bhh1[g * H_ + j];
    }
}

__global__ void k_zero() {
    int idx = blockIdx.x * blockDim.x + threadIdx.x;
    int stride = gridDim.x * blockDim.x;
    for (int i = idx; i < 2 * BH_; i += stride) {
        g_h0_hi[i] = bf16(0.f); g_h0_lo[i] = bf16(0.f);
        g_h1_hi[i] = bf16(0.f); g_h1_lo[i] = bf16(0.f);
        g_c0[i] = 0.f; g_c1[i] = 0.f;
    }
}

// ===================== input MLP stage 1 (K=6) ==============================
__global__ void k_in1(const float* __restrict__ x, const float* __restrict__ Wi1,
                      const float* __restrict__ bi1, bf16* __restrict__ u_hi,
                      bf16* __restrict__ u_lo) {
    int row = blockIdx.x;
    __shared__ float xs[LAG_];
    if (threadIdx.x < LAG_) xs[threadIdx.x] = x[row * LAG_ + threadIdx.x];
    __syncthreads();
    int j = threadIdx.x;
    float acc = bi1[j];
#pragma unroll
    for (int k = 0; k < LAG_; k++) acc = fmaf(xs[k], Wi1[j * LAG_ + k], acc);
    split_store(u_hi, u_lo, (size_t)row * H_ + j, fmaxf(acc, 0.f));
}

// ================== mma.sync split-bf16 GEMM + fused epilogues ==============
// C[128,64] tile of [Aa|Ab] @ W^T (W row-major [N][K], pre-split).
// MODE 0: out_f32 = D + bias                    (A0 projection, ldc)
// MODE 1: gates = D + addend -> LSTM cell (layer 0)
// MODE 2: gates = D + bias   -> LSTM cell (layer 1) + relu-split hr
// MODE 3: relu(D + bias) -> split bf16 out (ldh)
// MODE 4: relu(D + bias) -> f32 out (ldc)
__device__ __forceinline__ float sigm(float x) { return 1.f / (1.f + expf(-x)); }
__device__ __forceinline__ uint32_t smem_u32(const void* p) {
    uint32_t a;
    asm("{ .reg .u64 t; cvta.to.shared.u64 t, %1; cvt.u32.u64 %0, t; }" : "=r"(a) : "l"(p));
    return a;
}
__device__ __forceinline__ void ldm_x4(uint32_t* r, uint32_t addr) {
    asm volatile("ldmatrix.sync.aligned.m8n8.x4.shared.b16 {%0,%1,%2,%3}, [%4];"
                 : "=r"(r[0]), "=r"(r[1]), "=r"(r[2]), "=r"(r[3]) : "r"(addr));
}
__device__ __forceinline__ void ldm_x2(uint32_t* r, uint32_t addr) {
    asm volatile("ldmatrix.sync.aligned.m8n8.x2.shared.b16 {%0,%1}, [%2];"
                 : "=r"(r[0]), "=r"(r[1]) : "r"(addr));
}
__device__ __forceinline__ void mma16816(float* c, const uint32_t* a, const uint32_t* b) {
    asm volatile("mma.sync.aligned.m16n8k16.row.col.f32.bf16.bf16.f32 "
                 "{%0,%1,%2,%3}, {%4,%5,%6,%7}, {%8,%9}, {%0,%1,%2,%3};"
                 : "+f"(c[0]), "+f"(c[1]), "+f"(c[2]), "+f"(c[3])
                 : "r"(a[0]), "r"(a[1]), "r"(a[2]), "r"(a[3]), "r"(b[0]), "r"(b[1]));
}

#define AS_STRIDE 40     // halves per row (80 B = 5*16B, conflict-free ldmatrix)

template<int MODE>
__global__ void __launch_bounds__(256)
wm_gemm(const bf16* __restrict__ Aa_hi, const bf16* __restrict__ Aa_lo,
        const bf16* __restrict__ Ab_hi, const bf16* __restrict__ Ab_lo,
        const bf16* __restrict__ W_hi, const bf16* __restrict__ W_lo, int K,
        const float* __restrict__ addend, const float* __restrict__ bias,
        const float* __restrict__ c_prev, float* __restrict__ c_new,
        bf16* __restrict__ o_hi, bf16* __restrict__ o_lo,
        bf16* __restrict__ hr_hi, bf16* __restrict__ hr_lo,
        float* __restrict__ out_f32, int ldc) {
    __shared__ __align__(16) char smbuf[33024];
    bf16* Ash = (bf16*)(smbuf);             // [128][40]
    bf16* Asl = (bf16*)(smbuf + 10240);
    bf16* Wsh = (bf16*)(smbuf + 20480);     // [64][40]
    bf16* Wsl = (bf16*)(smbuf + 25600);
    float* Cst = (float*)smbuf;             // [128][64] reuse after loop

    int tid = threadIdx.x, wid = tid >> 5, lane = tid & 31;
    int wm = wid >> 2, wn = wid & 3;
    int bn = blockIdx.x, bm = blockIdx.y;
    uint32_t sb = smem_u32(smbuf);
    uint32_t sAh = sb, sAl = sb + 10240, sWh = sb + 20480, sWl = sb + 25600;

    float acc[4][2][4] = {};

    int ar = tid >> 2, acg = tid & 3;                 // A loader: 512 vec8/iter? no: 2 iters
    int wr = tid >> 2, wcg = tid & 3;                 // W loader: 256 vec8 exactly

    for (int k0 = 0; k0 < K; k0 += 32) {
        // ---- load A tile 128x32 (two halves of 64 rows each) ----
        const bf16* ph = (k0 < H_) ? Aa_hi : Ab_hi;
        const bf16* pl = (k0 < H_) ? Aa_lo : Ab_lo;
        int gk = (k0 < H_) ? k0 : k0 - H_;
#pragma unroll
        for (int it = 0; it < 2; it++) {
            int r = ar + it * 64;
            size_t gidx = (size_t)(bm * 128 + r) * H_ + gk + acg * 8;
            int soff = r * AS_STRIDE + acg * 8;
            *(uint4*)(Ash + soff) = *(const uint4*)(ph + gidx);
            *(uint4*)(Asl + soff) = *(const uint4*)(pl + gidx);
        }
        // ---- load W tile 64x32 ----
        {
            size_t gw = (size_t)(bn * 64 + wr) * K + k0 + wcg * 8;
            int soff = wr * AS_STRIDE + wcg * 8;
            *(uint4*)(Wsh + soff) = *(const uint4*)(W_hi + gw);
            *(uint4*)(Wsl + soff) = *(const uint4*)(W_lo + gw);
        }
        __syncthreads();

#pragma unroll
        for (int k16 = 0; k16 < 2; k16++) {
            uint32_t bh[2][2], bl[2][2];
#pragma unroll
            for (int nt = 0; nt < 2; nt++) {
                int row = wn * 16 + nt * 8 + (lane & 7);
                int colh = k16 * 16 + ((lane >> 3) & 1) * 8;
                uint32_t off = (uint32_t)(row * AS_STRIDE + colh) * 2;
                ldm_x2(bh[nt], sWh + off);
                ldm_x2(bl[nt], sWl + off);
            }
#pragma unroll
            for (int mt = 0; mt < 4; mt++) {
                int row = wm * 64 + mt * 16 + (lane & 7) + ((lane >> 3) & 1) * 8;
                int colh = k16 * 16 + (lane >> 4) * 8;
                uint32_t off = (uint32_t)(row * AS_STRIDE + colh) * 2;
                uint32_t ah[4], al[4];
                ldm_x4(ah, sAh + off);
                ldm_x4(al, sAl + off);
#pragma unroll
                for (int nt = 0; nt < 2; nt++) {
                    mma16816(acc[mt][nt], ah, bh[nt]);
                    mma16816(acc[mt][nt], ah, bl[nt]);
                    mma16816(acc[mt][nt], al, bh[nt]);
                }
            }
        }
        __syncthreads();
    }

    // ---- stage C to smem ----
#pragma unroll
    for (int mt = 0; mt < 4; mt++)
#pragma unroll
        for (int nt = 0; nt < 2; nt++) {
            int r0 = wm * 64 + mt * 16 + (lane >> 2);
            int c0 = wn * 16 + nt * 8 + (lane & 3) * 2;
            Cst[r0 * 64 + c0]     = acc[mt][nt][0];
            Cst[r0 * 64 + c0 + 1] = acc[mt][nt][1];
            Cst[(r0 + 8) * 64 + c0]     = acc[mt][nt][2];
            Cst[(r0 + 8) * 64 + c0 + 1] = acc[mt][nt][3];
        }
    __syncthreads();

    int grow0 = bm * 128, gcol0 = bn * 64;
    int row = tid >> 1, half = tid & 1;

    if (MODE == 0 || MODE == 4) {
        float* orow = out_f32 + (size_t)(grow0 + row) * ldc + gcol0 + half * 32;
        const float* crow = Cst + row * 64 + half * 32;
        const float* brow = bias + gcol0 + half * 32;
#pragma unroll
        for (int j = 0; j < 32; j += 4) {
            float4 v;
            v.x = crow[j + 0] + brow[j + 0];
            v.y = crow[j + 1] + brow[j + 1];
            v.z = crow[j + 2] + brow[j + 2];
            v.w = crow[j + 3] + brow[j + 3];
            if (MODE == 4) {
                v.x = fmaxf(v.x, 0.f); v.y = fmaxf(v.y, 0.f);
                v.z = fmaxf(v.z, 0.f); v.w = fmaxf(v.w, 0.f);
            }
            *(float4*)(orow + j) = v;
        }
    } else if (MODE == 3) {
        const float* crow = Cst + row * 64 + half * 32;
        const float* brow = bias + gcol0 + half * 32;
        size_t obase = (size_t)(grow0 + row) * ldc + gcol0 + half * 32;
        bf16 vh[32], vl[32];
#pragma unroll
        for (int j = 0; j < 32; j++) {
            float v = fmaxf(crow[j] + brow[j], 0.f);
            bf16 h = __float2bfloat16(v);
            vh[j] = h;
            vl[j] = __float2bfloat16(v - __bfloat162float(h));
        }
#pragma unroll
        for (int j = 0; j < 32; j += 8) {
            *(uint4*)(o_hi + obase + j) = *(uint4*)(vh + j);
            *(uint4*)(o_lo + obase + j) = *(uint4*)(vl + j);
        }
    } else {  // MODE 1 / 2: LSTM cell
#pragma unroll
        for (int u8 = 0; u8 < 8; u8++) {
            int ul = half * 8 + u8;                    // local unit 0..15
            float gg[4];
            const float* cp = Cst + row * 64 + ul * 4;
            if (MODE == 1) {
                float4 ad = *(const float4*)(addend + (size_t)(grow0 + row) * G_ + gcol0 + ul * 4);
                gg[0] = cp[0] + ad.x; gg[1] = cp[1] + ad.y;
                gg[2] = cp[2] + ad.z; gg[3] = cp[3] + ad.w;
            } else {
                const float* br = bias + gcol0 + ul * 4;
                gg[0] = cp[0] + br[0]; gg[1] = cp[1] + br[1];
                gg[2] = cp[2] + br[2]; gg[3] = cp[3] + br[3];
            }
            size_t ci = (size_t)(grow0 + row) * H_ + (gcol0 >> 2) + ul;
            float c = fmaf(sigm(gg[1]), c_prev[ci], sigm(gg[0]) * tanhf(gg[2]));
            c_new[ci] = c;
            float h = sigm(gg[3]) * tanhf(c);
            split_store(o_hi, o_lo, ci, h);
            if (MODE == 2) split_store(hr_hi, hr_lo, ci, fmaxf(h, 0.f));
        }
    }
}

// ===================== output head (N=6) ====================================
__global__ void k_out3(const float* __restrict__ Ain, const float* __restrict__ Wo3,
                       const float* __restrict__ bo3, float* __restrict__ y) {
    int row = blockIdx.x;
    int o = threadIdx.x >> 5, lane = threadIdx.x & 31;
    float acc = 0.f;
    const float* ar = Ain + (size_t)row * H_;
    const float* wr = Wo3 + o * H_;
#pragma unroll
    for (int k = lane; k < H_; k += 32) acc = fmaf(ar[k], wr[k], acc);
#pragma unroll
    for (int off = 16; off; off >>= 1) acc += __shfl_xor_sync(0xffffffffu, acc, off);
    if (lane == 0) y[row * LAG_ + o] = acc + bo3[o];
}

// ============================== host ========================================
extern "C" void kernel_launch(void* const* d_in, const int* in_sizes, int n_in,
                              void* d_out, int out_size) {
    const float* x    = (const float*)d_in[0];
    const float* Wi1  = (const float*)d_in[1];  const float* bi1 = (const float*)d_in[2];
    const float* Wi2  = (const float*)d_in[3];  const float* bi2 = (const float*)d_in[4];
    const float* Wi3  = (const float*)d_in[5];  const float* bi3 = (const float*)d_in[6];
    const float* Wih0 = (const float*)d_in[7];  const float* Whh0 = (const float*)d_in[8];
    const float* bih0 = (const float*)d_in[9];  const float* bhh0 = (const float*)d_in[10];
    const float* Wih1 = (const float*)d_in[11]; const float* Whh1 = (const float*)d_in[12];
    const float* bih1 = (const float*)d_in[13]; const float* bhh1 = (const float*)d_in[14];
    const float* Wo1  = (const float*)d_in[15]; const float* bo1 = (const float*)d_in[16];
    const float* Wo2  = (const float*)d_in[17]; const float* bo2 = (const float*)d_in[18];
    const float* Wo3  = (const float*)d_in[19]; const float* bo3 = (const float*)d_in[20];
    float* y = (float*)d_out;

    float *A0, *bufB, *c0b, *c1b, *b0r, *b1r;
    bf16 *u_hi, *u_lo, *v_hi, *v_lo, *hsr_hi, *hsr_lo;
    bf16 *h0_hi, *h0_lo, *h1_hi, *h1_lo;
    bf16 *Wi2h, *Wi2l, *Wi3h, *Wi3l, *Wo1h, *Wo1l, *Wo2h, *Wo2l;
    bf16 *Wih0h, *Wih0l, *Whh0h, *Whh0l, *W1h, *W1l;
    cudaGetSymbolAddress((void**)&A0,   g_A0);
    cudaGetSymbolAddress((void**)&bufB, g_bufB);
    cudaGetSymbolAddress((void**)&c0b,  g_c0);
    cudaGetSymbolAddress((void**)&c1b,  g_c1);
    cudaGetSymbolAddress((void**)&b0r,  g_b0r);
    cudaGetSymbolAddress((void**)&b1r,  g_b1r);
    cudaGetSymbolAddress((void**)&u_hi, g_u_hi);   cudaGetSymbolAddress((void**)&u_lo, g_u_lo);
    cudaGetSymbolAddress((void**)&v_hi, g_v_hi);   cudaGetSymbolAddress((void**)&v_lo, g_v_lo);
    cudaGetSymbolAddress((void**)&hsr_hi, g_hsr_hi); cudaGetSymbolAddress((void**)&hsr_lo, g_hsr_lo);
    cudaGetSymbolAddress((void**)&h0_hi, g_h0_hi); cudaGetSymbolAddress((void**)&h0_lo, g_h0_lo);
    cudaGetSymbolAddress((void**)&h1_hi, g_h1_hi); cudaGetSymbolAddress((void**)&h1_lo, g_h1_lo);
    cudaGetSymbolAddress((void**)&Wi2h, g_Wi2_hi); cudaGetSymbolAddress((void**)&Wi2l, g_Wi2_lo);
    cudaGetSymbolAddress((void**)&Wi3h, g_Wi3_hi); cudaGetSymbolAddress((void**)&Wi3l, g_Wi3_lo);
    cudaGetSymbolAddress((void**)&Wo1h, g_Wo1_hi); cudaGetSymbolAddress((void**)&Wo1l, g_Wo1_lo);
    cudaGetSymbolAddress((void**)&Wo2h, g_Wo2_hi); cudaGetSymbolAddress((void**)&Wo2l, g_Wo2_lo);
    cudaGetSymbolAddress((void**)&Wih0h, g_Wih0_hi); cudaGetSymbolAddress((void**)&Wih0l, g_Wih0_lo);
    cudaGetSymbolAddress((void**)&Whh0h, g_Whh0_hi); cudaGetSymbolAddress((void**)&Whh0l, g_Whh0_lo);
    cudaGetSymbolAddress((void**)&W1h,  g_W1_hi);  cudaGetSymbolAddress((void**)&W1l,  g_W1_lo);

    k_prep<<<512, 512>>>(Wi2, Wi3, Wo1, Wo2, Wih0, Whh0, bih0, bhh0,
                         Wih1, Whh1, bih1, bhh1);
    k_zero<<<512, 512>>>();

    // input MLP
    k_in1<<<NR_, H_>>>(x, Wi1, bi1, u_hi, u_lo);
    dim3 blk(256);
    dim3 gMLP(H_ / 64, NR_ / 128);               // (4, 1024)
    wm_gemm<3><<<gMLP, blk>>>(u_hi, u_lo, u_hi, u_lo, Wi2h, Wi2l, H_,
                              nullptr, bi2, nullptr, nullptr,
                              v_hi, v_lo, nullptr, nullptr, nullptr, H_);
    wm_gemm<3><<<gMLP, blk>>>(v_hi, v_lo, v_hi, v_lo, Wi3h, Wi3l, H_,
                              nullptr, bi3, nullptr, nullptr,
                              u_hi, u_lo, nullptr, nullptr, nullptr, H_);

    // hoisted layer-0 input projection: A0 = u @ Wih0r^T + b0r
    dim3 gA0(G_ / 64, NR_ / 128);                // (16, 1024)
    wm_gemm<0><<<gA0, blk>>>(u_hi, u_lo, u_hi, u_lo, Wih0h, Wih0l, H_,
                             nullptr, b0r, nullptr, nullptr,
                             nullptr, nullptr, nullptr, nullptr, A0, G_);

    // sequential recurrence
    dim3 gStep(G_ / 64, B_ / 128);               // (16, 8)
    for (int t = 0; t < T_; t++) {
        int r = t & 1, w = 1 - r;
        wm_gemm<1><<<gStep, blk>>>(h0_hi + r * BH_, h0_lo + r * BH_,
                                   h0_hi + r * BH_, h0_lo + r * BH_,
                                   Whh0h, Whh0l, H_,
                                   A0 + (size_t)t * B_ * G_, nullptr,
                                   c0b + r * BH_, c0b + w * BH_,
                                   h0_hi + w * BH_, h0_lo + w * BH_,
                                   nullptr, nullptr, nullptr, 0);
        wm_gemm<2><<<gStep, blk>>>(h0_hi + w * BH_, h0_lo + w * BH_,
                                   h1_hi + r * BH_, h1_lo + r * BH_,
                                   W1h, W1l, 2 * H_,
                                   nullptr, b1r,
                                   c1b + r * BH_, c1b + w * BH_,
                                   h1_hi + w * BH_, h1_lo + w * BH_,
                                   hsr_hi + (size_t)t * BH_, hsr_lo + (size_t)t * BH_,
                                   nullptr, 0);
    }

    // output MLP
    wm_gemm<3><<<gMLP, blk>>>(hsr_hi, hsr_lo, hsr_hi, hsr_lo, Wo1h, Wo1l, H_,
                              nullptr, bo1, nullptr, nullptr,
                              v_hi, v_lo, nullptr, nullptr, nullptr, H_);
    wm_gemm<4><<<gMLP, blk>>>(v_hi, v_lo, v_hi, v_lo, Wo2h, Wo2l, H_,
                              nullptr, bo2, nullptr, nullptr,
                              nullptr, nullptr, nullptr, nullptr, bufB, H_);
    k_out3<<<NR_, 192>>>(bufB, Wo3, bo3, y);
}

// round 4
// speedup vs baseline: 1.8507x; 1.2224x over previous
#include <cuda_runtime.h>
#include <cuda_bf16.h>
#include <math.h>
#include <stdint.h>

#define T_    128
#define B_    1024
#define LAG_  6
#define H_    256
#define G_    1024            // 4*H
#define NR_   (T_*B_)         // 131072
#define BH_   (B_*H_)         // 262144

typedef __nv_bfloat16 bf16;

// ============================ device scratch ================================
__device__ float g_A0[(size_t)NR_*G_];          // input-gate precompute
__device__ float g_bufB[NR_*H_];                // f32 staging before out3
__device__ bf16 g_u_hi[NR_*H_],  g_u_lo[NR_*H_];
__device__ bf16 g_v_hi[NR_*H_],  g_v_lo[NR_*H_];
__device__ bf16 g_hsr_hi[NR_*H_], g_hsr_lo[NR_*H_];   // relu(h1) split, per t
__device__ bf16 g_h0_hi[2*BH_], g_h0_lo[2*BH_];
__device__ bf16 g_h1_hi[2*BH_], g_h1_lo[2*BH_];
__device__ float g_c0[2*BH_], g_c1[2*BH_];
// split weights (row-major [N][K])
__device__ bf16 g_Wi2_hi[H_*H_], g_Wi2_lo[H_*H_];
__device__ bf16 g_Wi3_hi[H_*H_], g_Wi3_lo[H_*H_];
__device__ bf16 g_Wo1_hi[H_*H_], g_Wo1_lo[H_*H_];
__device__ bf16 g_Wo2_hi[H_*H_], g_Wo2_lo[H_*H_];
__device__ bf16 g_Wih0_hi[G_*H_], g_Wih0_lo[G_*H_];   // gate-interleaved rows
__device__ bf16 g_Whh0_hi[G_*H_], g_Whh0_lo[G_*H_];
__device__ bf16 g_W1_hi[G_*2*H_], g_W1_lo[G_*2*H_];   // [1024][512] = [Wih1|Whh1]
__device__ float g_b0r[G_], g_b1r[G_];

// ======================= low-level helpers ==================================
__device__ __forceinline__ void split_store(bf16* hi, bf16* lo, size_t i, float v) {
    bf16 h = __float2bfloat16(v);
    hi[i] = h;
    lo[i] = __float2bfloat16(v - __bfloat162float(h));
}
__device__ __forceinline__ float sigm(float x) { return 1.f / (1.f + expf(-x)); }
__device__ __forceinline__ uint32_t smem_u32(const void* p) {
    uint32_t a;
    asm("{ .reg .u64 t; cvta.to.shared.u64 t, %1; cvt.u32.u64 %0, t; }" : "=r"(a) : "l"(p));
    return a;
}
__device__ __forceinline__ void cp16(uint32_t dst, const void* src) {
    asm volatile("cp.async.cg.shared.global [%0], [%1], 16;" :: "r"(dst), "l"(src));
}
__device__ __forceinline__ void cp_commit() { asm volatile("cp.async.commit_group;" ::: "memory"); }
__device__ __forceinline__ void cp_wait1()  { asm volatile("cp.async.wait_group 1;" ::: "memory"); }
__device__ __forceinline__ void cp_wait0()  { asm volatile("cp.async.wait_group 0;" ::: "memory"); }
__device__ __forceinline__ void ldm_x4(uint32_t* r, uint32_t addr) {
    asm volatile("ldmatrix.sync.aligned.m8n8.x4.shared.b16 {%0,%1,%2,%3}, [%4];"
                 : "=r"(r[0]), "=r"(r[1]), "=r"(r[2]), "=r"(r[3]) : "r"(addr));
}
__device__ __forceinline__ void mma16816(float* c, const uint32_t* a, const uint32_t* b) {
    asm volatile("mma.sync.aligned.m16n8k16.row.col.f32.bf16.bf16.f32 "
                 "{%0,%1,%2,%3}, {%4,%5,%6,%7}, {%8,%9}, {%0,%1,%2,%3};"
                 : "+f"(c[0]), "+f"(c[1]), "+f"(c[2]), "+f"(c[3])
                 : "r"(a[0]), "r"(a[1]), "r"(a[2]), "r"(a[3]), "r"(b[0]), "r"(b[1]));
}

// stage layout: Ash[128][40], Asl, Wsh[64][40], Wsl — 30720 B per stage, 3 stages
#define ASTR 40
#define STG_BYTES 30720
#define SMEM_SZ   (3 * STG_BYTES)

// ======== shared mainloop: 128x64 C tile of [Aa|Ab](row-major, ld=H_) @ W^T =
struct CoreArgs {
    const bf16 *Aa_hi, *Aa_lo, *Ab_hi, *Ab_lo, *W_hi, *W_lo;
    int K;
};

__device__ __forceinline__ void gemm_core(const CoreArgs& g, char* smbuf,
                                          int bm, int bn, float acc[4][2][4]) {
    int tid = threadIdx.x, wid = tid >> 5, lane = tid & 31;
    int wm = wid >> 2, wn = wid & 3;
    uint32_t sb0 = smem_u32(smbuf);
    int n = g.K >> 5;

    int r0 = tid >> 2, cg8 = (tid & 3) << 3;
    uint32_t so = (uint32_t)(r0 * ASTR + cg8) * 2;

    auto load_chunk = [&](int c, int stage) {
        uint32_t sb = sb0 + stage * STG_BYTES;
        int k0 = c << 5;
        const bf16 *ph, *pl; int gk;
        if (k0 < H_) { ph = g.Aa_hi; pl = g.Aa_lo; gk = k0; }
        else         { ph = g.Ab_hi; pl = g.Ab_lo; gk = k0 - H_; }
        size_t ga = (size_t)(bm * 128 + r0) * H_ + gk + cg8;
        cp16(sb + so,         ph + ga);
        cp16(sb + 10240 + so, pl + ga);
        size_t ga2 = ga + (size_t)64 * H_;
        uint32_t so2 = so + 64 * ASTR * 2;
        cp16(sb + so2,         ph + ga2);
        cp16(sb + 10240 + so2, pl + ga2);
        size_t gw = (size_t)(bn * 64 + r0) * g.K + k0 + cg8;
        cp16(sb + 20480 + so, g.W_hi + gw);
        cp16(sb + 25600 + so, g.W_lo + gw);
    };

    auto compute_chunk = [&](int stage) {
        uint32_t sb = sb0 + stage * STG_BYTES;
#pragma unroll
        for (int k16 = 0; k16 < 2; k16++) {
            uint32_t bh4[4], bl4[4];
            {
                int row = wn * 16 + ((lane >> 4) & 1) * 8 + (lane & 7);
                int colh = k16 * 16 + ((lane >> 3) & 1) * 8;
                uint32_t off = (uint32_t)(row * ASTR + colh) * 2;
                ldm_x4(bh4, sb + 20480 + off);
                ldm_x4(bl4, sb + 25600 + off);
            }
#pragma unroll
            for (int mt = 0; mt < 4; mt++) {
                int row = wm * 64 + mt * 16 + (lane & 7) + ((lane >> 3) & 1) * 8;
                int colh = k16 * 16 + ((lane >> 4) & 1) * 8;
                uint32_t off = (uint32_t)(row * ASTR + colh) * 2;
                uint32_t ah[4], al[4];
                ldm_x4(ah, sb + off);
                ldm_x4(al, sb + 10240 + off);
                mma16816(acc[mt][0], ah, bh4);
                mma16816(acc[mt][0], ah, bl4);
                mma16816(acc[mt][0], al, bh4);
                mma16816(acc[mt][1], ah, bh4 + 2);
                mma16816(acc[mt][1], ah, bl4 + 2);
                mma16816(acc[mt][1], al, bh4 + 2);
            }
        }
    };

    load_chunk(0, 0); cp_commit();
    if (n > 1) load_chunk(1, 1);
    cp_commit();
    for (int i = 0; i < n; i++) {
        cp_wait1();
        __syncthreads();
        if (i + 2 < n) load_chunk(i + 2, (i + 2) % 3);
        cp_commit();
        compute_chunk(i % 3);
    }
    cp_wait0();
    __syncthreads();
}

__device__ __forceinline__ void stage_C(float* Cst, const float acc[4][2][4],
                                        int wm, int wn, int lane) {
#pragma unroll
    for (int mt = 0; mt < 4; mt++)
#pragma unroll
        for (int nt = 0; nt < 2; nt++) {
            int r0 = wm * 64 + mt * 16 + (lane >> 2);
            int c0 = wn * 16 + nt * 8 + (lane & 3) * 2;
            Cst[r0 * 64 + c0]       = acc[mt][nt][0];
            Cst[r0 * 64 + c0 + 1]   = acc[mt][nt][1];
            Cst[(r0 + 8) * 64 + c0]     = acc[mt][nt][2];
            Cst[(r0 + 8) * 64 + c0 + 1] = acc[mt][nt][3];
        }
}

// LSTM-cell epilogue from staged C (per thread: row=tid>>1, 16 units half)
__device__ __forceinline__ void lstm_epilogue(const float* Cst, int grow0, int gcol0,
                                              const float* addend, const float* bias,
                                              const float* c_prev, float* c_new,
                                              bf16* o_hi, bf16* o_lo,
                                              bf16* hr_hi, bf16* hr_lo) {
    int tid = threadIdx.x;
    int row = tid >> 1, half = tid & 1;
#pragma unroll
    for (int u8 = 0; u8 < 8; u8++) {
        int ul = half * 8 + u8;
        float gg[4];
        const float* cp = Cst + row * 64 + ul * 4;
        if (addend) {
            float4 ad = *(const float4*)(addend + (size_t)(grow0 + row) * G_ + gcol0 + ul * 4);
            gg[0] = cp[0] + ad.x; gg[1] = cp[1] + ad.y;
            gg[2] = cp[2] + ad.z; gg[3] = cp[3] + ad.w;
        } else {
            const float* br = bias + gcol0 + ul * 4;
            gg[0] = cp[0] + br[0]; gg[1] = cp[1] + br[1];
            gg[2] = cp[2] + br[2]; gg[3] = cp[3] + br[3];
        }
        size_t ci = (size_t)(grow0 + row) * H_ + (gcol0 >> 2) + ul;
        float c = fmaf(sigm(gg[1]), c_prev[ci], sigm(gg[0]) * tanhf(gg[2]));
        c_new[ci] = c;
        float h = sigm(gg[3]) * tanhf(c);
        split_store(o_hi, o_lo, ci, h);
        if (hr_hi) split_store(hr_hi, hr_lo, ci, fmaxf(h, 0.f));
    }
}

// ================= generic pipelined GEMM kernel (MLP / A0) =================
// MODE 0: out_f32 = D + bias (ldc)
// MODE 3: relu(D + bias) -> split bf16 (ldc)
// MODE 4: relu(D + bias) -> f32 (ldc)
template<int MODE>
__global__ void __launch_bounds__(256, 2)
wm_gemm(const bf16* __restrict__ Aa_hi, const bf16* __restrict__ Aa_lo,
        const bf16* __restrict__ Ab_hi, const bf16* __restrict__ Ab_lo,
        const bf16* __restrict__ W_hi, const bf16* __restrict__ W_lo, int K,
        const float* __restrict__ bias,
        bf16* __restrict__ o_hi, bf16* __restrict__ o_lo,
        float* __restrict__ out_f32, int ldc) {
    extern __shared__ __align__(16) char smbuf[];
    int tid = threadIdx.x, wid = tid >> 5, lane = tid & 31;
    int wm = wid >> 2, wn = wid & 3;
    int bn = blockIdx.x, bm = blockIdx.y;

    float acc[4][2][4] = {};
    CoreArgs g{Aa_hi, Aa_lo, Ab_hi, Ab_lo, W_hi, W_lo, K};
    gemm_core(g, smbuf, bm, bn, acc);

    float* Cst = (float*)smbuf;
    stage_C(Cst, acc, wm, wn, lane);
    __syncthreads();

    int grow0 = bm * 128, gcol0 = bn * 64;
    int row = tid >> 1, half = tid & 1;

    if (MODE == 0 || MODE == 4) {
        float* orow = out_f32 + (size_t)(grow0 + row) * ldc + gcol0 + half * 32;
        const float* crow = Cst + row * 64 + half * 32;
        const float* brow = bias + gcol0 + half * 32;
#pragma unroll
        for (int j = 0; j < 32; j += 4) {
            float4 v;
            v.x = crow[j + 0] + brow[j + 0];
            v.y = crow[j + 1] + brow[j + 1];
            v.z = crow[j + 2] + brow[j + 2];
            v.w = crow[j + 3] + brow[j + 3];
            if (MODE == 4) {
                v.x = fmaxf(v.x, 0.f); v.y = fmaxf(v.y, 0.f);
                v.z = fmaxf(v.z, 0.f); v.w = fmaxf(v.w, 0.f);
            }
            *(float4*)(orow + j) = v;
        }
    } else {  // MODE 3
        const float* crow = Cst + row * 64 + half * 32;
        const float* brow = bias + gcol0 + half * 32;
        size_t obase = (size_t)(grow0 + row) * ldc + gcol0 + half * 32;
        bf16 vh[32], vl[32];
#pragma unroll
        for (int j = 0; j < 32; j++) {
            float v = fmaxf(crow[j] + brow[j], 0.f);
            bf16 h = __float2bfloat16(v);
            vh[j] = h;
            vl[j] = __float2bfloat16(v - __bfloat162float(h));
        }
#pragma unroll
        for (int j = 0; j < 32; j += 8) {
            *(uint4*)(o_hi + obase + j) = *(uint4*)(vh + j);
            *(uint4*)(o_lo + obase + j) = *(uint4*)(vl + j);
        }
    }
}

// ========= combined recurrence step: role0 = L0(t0), role1 = L1(t1) =========
__global__ void __launch_bounds__(256, 2)
k_step(int t0, int t1) {
    extern __shared__ __align__(16) char smbuf[];
    int role = blockIdx.z;
    int t = role ? t1 : t0;
    if (t < 0) return;

    int tid = threadIdx.x, wid = tid >> 5, lane = tid & 31;
    int wm = wid >> 2, wn = wid & 3;
    int bn = blockIdx.x, bm = blockIdx.y;
    int r = t & 1, w = 1 - r;

    CoreArgs g;
    const float *addend, *bias, *c_prev;
    float* c_new;
    bf16 *o_hi, *o_lo, *hr_hi, *hr_lo;
    if (role == 0) {
        g = {g_h0_hi + r * BH_, g_h0_lo + r * BH_,
             g_h0_hi + r * BH_, g_h0_lo + r * BH_,
             g_Whh0_hi, g_Whh0_lo, H_};
        addend = g_A0 + (size_t)t * B_ * G_;
        bias = nullptr;
        c_prev = g_c0 + r * BH_; c_new = g_c0 + w * BH_;
        o_hi = g_h0_hi + w * BH_; o_lo = g_h0_lo + w * BH_;
        hr_hi = nullptr; hr_lo = nullptr;
    } else {
        g = {g_h0_hi + w * BH_, g_h0_lo + w * BH_,     // h0(t) lives in slot w=1-(t&1)
             g_h1_hi + r * BH_, g_h1_lo + r * BH_,
             g_W1_hi, g_W1_lo, 2 * H_};
        addend = nullptr;
        bias = g_b1r;
        c_prev = g_c1 + r * BH_; c_new = g_c1 + w * BH_;
        o_hi = g_h1_hi + w * BH_; o_lo = g_h1_lo + w * BH_;
        hr_hi = g_hsr_hi + (size_t)t * BH_; hr_lo = g_hsr_lo + (size_t)t * BH_;
    }

    float acc[4][2][4] = {};
    gemm_core(g, smbuf, bm, bn, acc);

    float* Cst = (float*)smbuf;
    stage_C(Cst, acc, wm, wn, lane);
    __syncthreads();

    lstm_epilogue(Cst, bm * 128, bn * 64, addend, bias, c_prev, c_new,
                  o_hi, o_lo, hr_hi, hr_lo);
}

// ======================= prep: split + gate reorder =========================
__global__ void k_prep(const float* __restrict__ Wi2, const float* __restrict__ Wi3,
                       const float* __restrict__ Wo1, const float* __restrict__ Wo2,
                       const float* __restrict__ Wih0, const float* __restrict__ Whh0,
                       const float* __restrict__ bih0, const float* __restrict__ bhh0,
                       const float* __restrict__ Wih1, const float* __restrict__ Whh1,
                       const float* __restrict__ bih1, const float* __restrict__ bhh1) {
    int idx = blockIdx.x * blockDim.x + threadIdx.x;
    int stride = gridDim.x * blockDim.x;
    for (int i = idx; i < H_ * H_; i += stride) {
        split_store(g_Wi2_hi, g_Wi2_lo, i, Wi2[i]);
        split_store(g_Wi3_hi, g_Wi3_lo, i, Wi3[i]);
        split_store(g_Wo1_hi, g_Wo1_lo, i, Wo1[i]);
        split_store(g_Wo2_hi, g_Wo2_lo, i, Wo2[i]);
    }
    for (int i = idx; i < G_ * H_; i += stride) {
        int rr = i / H_, k = i - rr * H_;
        int j = rr >> 2, gg = rr & 3;
        int src = (gg * H_ + j) * H_ + k;
        split_store(g_Wih0_hi, g_Wih0_lo, i, Wih0[src]);
        split_store(g_Whh0_hi, g_Whh0_lo, i, Whh0[src]);
    }
    for (int i = idx; i < G_ * 2 * H_; i += stride) {
        int rr = i / (2 * H_), k = i - rr * (2 * H_);
        int j = rr >> 2, gg = rr & 3;
        float v = (k < H_) ? Wih1[(gg * H_ + j) * H_ + k]
                           : Whh1[(gg * H_ + j) * H_ + (k - H_)];
        split_store(g_W1_hi, g_W1_lo, i, v);
    }
    if (idx < G_) {
        int j = idx >> 2, gg = idx & 3;
        g_b0r[idx] = bih0[gg * H_ + j] + bhh0[gg * H_ + j];
        g_b1r[idx] = bih1[gg * H_ + j] + bhh1[gg * H_ + j];
    }
}

__global__ void k_zero() {
    int idx = blockIdx.x * blockDim.x + threadIdx.x;
    int stride = gridDim.x * blockDim.x;
    for (int i = idx; i < 2 * BH_; i += stride) {
        g_h0_hi[i] = bf16(0.f); g_h0_lo[i] = bf16(0.f);
        g_h1_hi[i] = bf16(0.f); g_h1_lo[i] = bf16(0.f);
        g_c0[i] = 0.f; g_c1[i] = 0.f;
    }
}

// ===================== input MLP stage 1 (K=6) ==============================
__global__ void __launch_bounds__(256)
k_in1(const float* __restrict__ x, const float* __restrict__ Wi1,
      const float* __restrict__ bi1) {
    __shared__ float Ws[H_ * LAG_];
    __shared__ float bs[H_];
    int tid = threadIdx.x;
    for (int i = tid; i < H_ * LAG_; i += 256) Ws[i] = Wi1[i];
    if (tid < H_) bs[tid] = bi1[tid];
    __syncthreads();
    int j = tid;
    for (int rr = 0; rr < 64; rr++) {
        int row = blockIdx.x * 64 + rr;
        const float* xr = x + (size_t)row * LAG_;
        float acc = bs[j];
#pragma unroll
        for (int k = 0; k < LAG_; k++) acc = fmaf(xr[k], Ws[j * LAG_ + k], acc);
        split_store(g_u_hi, g_u_lo, (size_t)row * H_ + j, fmaxf(acc, 0.f));
    }
}

// ===================== output head (N=6) ====================================
__global__ void __launch_bounds__(256)
k_out3(const float* __restrict__ Ain, const float* __restrict__ Wo3,
       const float* __restrict__ bo3, float* __restrict__ y) {
    __shared__ float Ws[LAG_ * H_];
    int tid = threadIdx.x;
    for (int i = tid; i < LAG_ * H_; i += 256) Ws[i] = Wo3[i];
    __syncthreads();
    int wrp = tid >> 5, lane = tid & 31;
    int row = blockIdx.x * 8 + wrp;
    const float* ar = Ain + (size_t)row * H_;
    float acc[LAG_] = {};
    for (int k = lane; k < H_; k += 32) {
        float a = ar[k];
#pragma unroll
        for (int o = 0; o < LAG_; o++) acc[o] = fmaf(a, Ws[o * H_ + k], acc[o]);
    }
#pragma unroll
    for (int o = 0; o < LAG_; o++) {
        float v = acc[o];
#pragma unroll
        for (int off = 16; off; off >>= 1) v += __shfl_xor_sync(0xffffffffu, v, off);
        if (lane == 0) y[(size_t)row * LAG_ + o] = v + bo3[o];
    }
}

// ============================== host ========================================
extern "C" void kernel_launch(void* const* d_in, const int* in_sizes, int n_in,
                              void* d_out, int out_size) {
    const float* x    = (const float*)d_in[0];
    const float* Wi1  = (const float*)d_in[1];  const float* bi1 = (const float*)d_in[2];
    const float* Wi2  = (const float*)d_in[3];  const float* bi2 = (const float*)d_in[4];
    const float* Wi3  = (const float*)d_in[5];  const float* bi3 = (const float*)d_in[6];
    const float* Wih0 = (const float*)d_in[7];  const float* Whh0 = (const float*)d_in[8];
    const float* bih0 = (const float*)d_in[9];  const float* bhh0 = (const float*)d_in[10];
    const float* Wih1 = (const float*)d_in[11]; const float* Whh1 = (const float*)d_in[12];
    const float* bih1 = (const float*)d_in[13]; const float* bhh1 = (const float*)d_in[14];
    const float* Wo1  = (const float*)d_in[15]; const float* bo1 = (const float*)d_in[16];
    const float* Wo2  = (const float*)d_in[17]; const float* bo2 = (const float*)d_in[18];
    const float* Wo3  = (const float*)d_in[19]; const float* bo3 = (const float*)d_in[20];
    float* y = (float*)d_out;

    static int smem_set = 0;
    if (!smem_set) {
        cudaFuncSetAttribute(wm_gemm<0>, cudaFuncAttributeMaxDynamicSharedMemorySize, SMEM_SZ);
        cudaFuncSetAttribute(wm_gemm<3>, cudaFuncAttributeMaxDynamicSharedMemorySize, SMEM_SZ);
        cudaFuncSetAttribute(wm_gemm<4>, cudaFuncAttributeMaxDynamicSharedMemorySize, SMEM_SZ);
        cudaFuncSetAttribute(k_step,     cudaFuncAttributeMaxDynamicSharedMemorySize, SMEM_SZ);
        smem_set = 1;
    }

    float *A0, *bufB, *b0r, *b1r;
    bf16 *u_hi, *u_lo, *v_hi, *v_lo, *hsr_hi, *hsr_lo;
    bf16 *Wi2h, *Wi2l, *Wi3h, *Wi3l, *Wo1h, *Wo1l, *Wo2h, *Wo2l, *Wih0h, *Wih0l;
    cudaGetSymbolAddress((void**)&A0,   g_A0);
    cudaGetSymbolAddress((void**)&bufB, g_bufB);
    cudaGetSymbolAddress((void**)&b0r,  g_b0r);
    cudaGetSymbolAddress((void**)&b1r,  g_b1r);
    cudaGetSymbolAddress((void**)&u_hi, g_u_hi);   cudaGetSymbolAddress((void**)&u_lo, g_u_lo);
    cudaGetSymbolAddress((void**)&v_hi, g_v_hi);   cudaGetSymbolAddress((void**)&v_lo, g_v_lo);
    cudaGetSymbolAddress((void**)&hsr_hi, g_hsr_hi); cudaGetSymbolAddress((void**)&hsr_lo, g_hsr_lo);
    cudaGetSymbolAddress((void**)&Wi2h, g_Wi2_hi); cudaGetSymbolAddress((void**)&Wi2l, g_Wi2_lo);
    cudaGetSymbolAddress((void**)&Wi3h, g_Wi3_hi); cudaGetSymbolAddress((void**)&Wi3l, g_Wi3_lo);
    cudaGetSymbolAddress((void**)&Wo1h, g_Wo1_hi); cudaGetSymbolAddress((void**)&Wo1l, g_Wo1_lo);
    cudaGetSymbolAddress((void**)&Wo2h, g_Wo2_hi); cudaGetSymbolAddress((void**)&Wo2l, g_Wo2_lo);
    cudaGetSymbolAddress((void**)&Wih0h, g_Wih0_hi); cudaGetSymbolAddress((void**)&Wih0l, g_Wih0_lo);

    k_prep<<<512, 512>>>(Wi2, Wi3, Wo1, Wo2, Wih0, Whh0, bih0, bhh0,
                         Wih1, Whh1, bih1, bhh1);
    k_zero<<<512, 512>>>();

    // input MLP
    k_in1<<<NR_ / 64, 256>>>(x, Wi1, bi1);
    dim3 blk(256);
    dim3 gMLP(H_ / 64, NR_ / 128);               // (4, 1024)
    wm_gemm<3><<<gMLP, blk, SMEM_SZ>>>(u_hi, u_lo, u_hi, u_lo, Wi2h, Wi2l, H_,
                                       bi2, v_hi, v_lo, nullptr, H_);
    wm_gemm<3><<<gMLP, blk, SMEM_SZ>>>(v_hi, v_lo, v_hi, v_lo, Wi3h, Wi3l, H_,
                                       bi3, u_hi, u_lo, nullptr, H_);

    // hoisted layer-0 input projection: A0 = u @ Wih0r^T + b0r
    dim3 gA0(G_ / 64, NR_ / 128);                // (16, 1024)
    wm_gemm<0><<<gA0, blk, SMEM_SZ>>>(u_hi, u_lo, u_hi, u_lo, Wih0h, Wih0l, H_,
                                      b0r, nullptr, nullptr, A0, G_);

    // pipelined recurrence: launch s computes L0(s) and L1(s-1) concurrently
    dim3 gStep(G_ / 64, B_ / 128, 2);            // (16, 8, 2) = 256 CTAs
    for (int s = 0; s <= T_; s++) {
        k_step<<<gStep, blk, SMEM_SZ>>>((s < T_) ? s : -1, s - 1);
    }

    // output MLP
    wm_gemm<3><<<gMLP, blk, SMEM_SZ>>>(hsr_hi, hsr_lo, hsr_hi, hsr_lo, Wo1h, Wo1l, H_,
                                       bo1, v_hi, v_lo, nullptr, H_);
    wm_gemm<4><<<gMLP, blk, SMEM_SZ>>>(v_hi, v_lo, v_hi, v_lo, Wo2h, Wo2l, H_,
                                       bo2, nullptr, nullptr, bufB, H_);
    k_out3<<<NR_ / 8, 256>>>(bufB, Wo3, bo3, y);
}